// round 13
// baseline (speedup 1.0000x reference)
#include <cuda_runtime.h>
#include <cuda_fp16.h>
#include <cstdint>

#define NN   1024      // nodes
#define EE   2048      // raw edges
#define ET   3072      // edges + self loops
#define HH   32        // heads
#define CMX  1028      // max per-head channel dim
#define KPMX 1088      // max padded K
#define BMAX 16842752  // 32896*512 max weight elements

// ---------------- scratch (device globals; no allocation allowed) ----------------
__device__ __half   g_xl[(size_t)NN * HH * CMX];
__device__ __half   g_xr[(size_t)NN * HH * CMX];
__device__ float    g_alpha[ET * HH];
__device__ int      g_src[ET];
__device__ int      g_dst[ET];
__device__ int      g_rank[ET];
__device__ int      g_deg[NN];
__device__ int      g_rowptr[NN + 1];
__device__ int      g_eid[ET];
__device__ int      g_is64;
__device__ __half   g_ah[NN * KPMX];
__device__ __half   g_b0[BMAX];
__device__ __half   g_b1[BMAX];

// ---------------- edge dtype detection ----------------
__global__ void detect_dtype_kernel(const void* ei) {
    __shared__ int bad;
    if (threadIdx.x == 0) bad = 0;
    __syncthreads();
    const long long* p = (const long long*)ei;
    for (int i = threadIdx.x; i < EE; i += blockDim.x) {
        long long v = p[i];
        if (v < 0 || v >= NN) bad = 1;
    }
    __syncthreads();
    if (threadIdx.x == 0) g_is64 = !bad;
}

// ---------------- edge build + deg zero ----------------
__global__ void build_edges_kernel(const void* ei) {
    int i = blockIdx.x * blockDim.x + threadIdx.x;
    if (i < ET) {
        if (i < EE) {
            if (g_is64) {
                const long long* p = (const long long*)ei;
                g_src[i] = (int)p[i];
                g_dst[i] = (int)p[EE + i];
            } else {
                const int* p = (const int*)ei;
                g_src[i] = p[i];
                g_dst[i] = p[EE + i];
            }
        } else {
            g_src[i] = i - EE;
            g_dst[i] = i - EE;
        }
    }
    if (i < NN) g_deg[i] = 0;
}

// ---------------- CSR build (deterministic) ----------------
__global__ void csr_rank_kernel() {
    __shared__ int sd[ET];
    int tid = threadIdx.x;
    for (int i = tid; i < ET; i += blockDim.x) sd[i] = g_dst[i];
    __syncthreads();
    int e = blockIdx.x * blockDim.x + tid;
    if (e < ET) {
        int d = sd[e], r = 0;
        for (int e2 = 0; e2 < e; e2++) r += (sd[e2] == d);
        g_rank[e] = r;
        atomicAdd(&g_deg[d], 1);
    }
}

// scan + place fused: single block of NN threads
__global__ void csr_scan_place_kernel() {
    __shared__ int s[NN];
    __shared__ int start[NN];
    int t = threadIdx.x;
    s[t] = g_deg[t];
    __syncthreads();
    for (int o = 1; o < NN; o <<= 1) {
        int v = (t >= o) ? s[t - o] : 0;
        __syncthreads();
        s[t] += v;
        __syncthreads();
    }
    g_rowptr[t + 1] = s[t];
    start[t] = s[t] - g_deg[t];
    if (t == 0) g_rowptr[0] = 0;
    __syncthreads();
    for (int e = t; e < ET; e += NN)
        g_eid[start[g_dst[e]] + g_rank[e]] = e;
}

// ---------------- fp32 [K,Nn] -> fp16, row pad to Kp; pair fused via blockIdx.y ----------------
__global__ void convertB_kernel(const float* __restrict__ B0,
                                const float* __restrict__ B1,
                                int K, int Nn, int Kp) {
    int i4 = blockIdx.x * blockDim.x + threadIdx.x;
    int tot = (Kp * Nn) >> 2;
    if (i4 >= tot) return;
    const float* src = blockIdx.y ? B1 : B0;
    __half* dst = blockIdx.y ? g_b1 : g_b0;
    int n4 = Nn >> 2;
    int r = i4 / n4, c4 = (i4 - r * n4) << 2;
    float v[4];
    if (r < K) {
        float4 f = *(const float4*)(src + (size_t)r * Nn + c4);
        v[0] = f.x; v[1] = f.y; v[2] = f.z; v[3] = f.w;
    } else {
        v[0] = v[1] = v[2] = v[3] = 0.f;
    }
    size_t o = (size_t)r * Nn + c4;
    *(__half2*)(dst + o)     = __halves2half2(__float2half_rn(v[0]), __float2half_rn(v[1]));
    *(__half2*)(dst + o + 2) = __halves2half2(__float2half_rn(v[2]), __float2half_rn(v[3]));
}

// ---------------- tensor-core GEMM (plain fp16, fp32 accum, cp.async pipeline) ----------------
#define ASTR 40
#define BSTR 136
#define AOFF 0
#define BOFF 10240
#define BUFSZ 18944
#define DSMEM (2 * BUFSZ)

#define LDMX4(R0,R1,R2,R3,ADDR) \
    asm volatile("ldmatrix.sync.aligned.m8n8.x4.shared.b16 {%0,%1,%2,%3}, [%4];" \
        : "=r"(R0), "=r"(R1), "=r"(R2), "=r"(R3) : "r"(ADDR))
#define LDMX2T(R0,R1,ADDR) \
    asm volatile("ldmatrix.sync.aligned.m8n8.x2.trans.shared.b16 {%0,%1}, [%2];" \
        : "=r"(R0), "=r"(R1) : "r"(ADDR))
#define MMA16816(C0,C1,C2,C3,A0,A1,A2,A3,B0,B1) \
    asm volatile("mma.sync.aligned.m16n8k16.row.col.f32.f16.f16.f32 " \
        "{%0,%1,%2,%3}, {%4,%5,%6,%7}, {%8,%9}, {%0,%1,%2,%3};" \
        : "+f"(C0), "+f"(C1), "+f"(C2), "+f"(C3) \
        : "r"(A0), "r"(A1), "r"(A2), "r"(A3), "r"(B0), "r"(B1))
#define CP16(SADDR, GPTR) \
    asm volatile("cp.async.ca.shared.global [%0], [%1], 16;" :: "r"(SADDR), "l"(GPTR))

__global__ __launch_bounds__(256) void tc_gemm_kernel(
    const __half* __restrict__ Ah,
    const __half* __restrict__ B0, const __half* __restrict__ B1,
    const float* __restrict__ bias0, const float* __restrict__ bias1,
    void* __restrict__ C0v, void* __restrict__ C1v,
    int Nn, int Kp, int act, int hout)
{
    extern __shared__ char smem[];
    const uint32_t sbase = (uint32_t)__cvta_generic_to_shared(smem);

    const int tid  = threadIdx.x;
    const int warp = tid >> 5;
    const int lane = tid & 31;
    const int wm = (warp >> 2) * 64;
    const int wn = (warp & 3) * 32;
    const int bx = blockIdx.x * 128;
    const int by = blockIdx.y * 128;
    const int z  = blockIdx.z;

    const __half* B = z ? B1 : B0;
    const float* bias = z ? bias1 : bias0;
    void* Cv = z ? C1v : C0v;

    float acc[4][4][4];
#pragma unroll
    for (int mi = 0; mi < 4; mi++)
#pragma unroll
        for (int ni = 0; ni < 4; ni++)
#pragma unroll
            for (int k = 0; k < 4; k++) acc[mi][ni][k] = 0.f;

    const int nc = Kp >> 5;

    auto load_tile = [&](int c, int b) {
        const int k0 = c << 5;
        const uint32_t base = sbase + b * BUFSZ;
#pragma unroll
        for (int j = 0; j < 2; j++) {
            int idx = tid + j * 256;
            int row = idx >> 2, seg = idx & 3;
            size_t go = (size_t)(by + row) * Kp + k0 + seg * 8;
            uint32_t so = base + (uint32_t)(row * ASTR + seg * 8) * 2;
            CP16(so + AOFF, Ah + go);
        }
#pragma unroll
        for (int j = 0; j < 2; j++) {
            int idx = tid + j * 256;
            int row = idx >> 4, seg = idx & 15;
            size_t go = (size_t)(k0 + row) * Nn + bx + seg * 8;
            uint32_t so = base + (uint32_t)(row * BSTR + seg * 8) * 2;
            CP16(so + BOFF, B + go);
        }
        asm volatile("cp.async.commit_group;" ::: "memory");
    };

    const int r8 = lane & 7;
    const int gA = lane >> 3;
    const int gB = (lane >> 3) & 1;

    load_tile(0, 0);

    for (int c = 0; c < nc; c++) {
        const int b = c & 1;
        if (c + 1 < nc) {
            load_tile(c + 1, (c + 1) & 1);
            asm volatile("cp.async.wait_group 1;" ::: "memory");
        } else {
            asm volatile("cp.async.wait_group 0;" ::: "memory");
        }
        __syncthreads();

        const uint32_t base = sbase + b * BUFSZ;
#pragma unroll
        for (int ks = 0; ks < 2; ks++) {
            const int ko = ks * 16;
            uint32_t ah[4][4], bb[4][2];
#pragma unroll
            for (int mi = 0; mi < 4; mi++) {
                int row = wm + mi * 16 + r8 + (gA & 1) * 8;
                int col = ko + (gA >> 1) * 8;
                uint32_t off = (uint32_t)(row * ASTR + col) * 2;
                LDMX4(ah[mi][0], ah[mi][1], ah[mi][2], ah[mi][3], base + AOFF + off);
            }
#pragma unroll
            for (int ni = 0; ni < 4; ni++) {
                int row = ko + gB * 8 + r8;
                int col = wn + ni * 8;
                uint32_t off = (uint32_t)(row * BSTR + col) * 2;
                LDMX2T(bb[ni][0], bb[ni][1], base + BOFF + off);
            }
#pragma unroll
            for (int mi = 0; mi < 4; mi++) {
#pragma unroll
                for (int ni = 0; ni < 4; ni++) {
                    float* cc = acc[mi][ni];
                    MMA16816(cc[0], cc[1], cc[2], cc[3],
                             ah[mi][0], ah[mi][1], ah[mi][2], ah[mi][3],
                             bb[ni][0], bb[ni][1]);
                }
            }
        }
        __syncthreads();
    }

    const int g = lane >> 2, tig = lane & 3;
#pragma unroll
    for (int mi = 0; mi < 4; mi++) {
#pragma unroll
        for (int ni = 0; ni < 4; ni++) {
            int row = by + wm + mi * 16 + g;
            int col = bx + wn + ni * 8 + tig * 2;
            float bv0 = bias[col], bv1 = bias[col + 1];
            float v0 = acc[mi][ni][0] + bv0;
            float v1 = acc[mi][ni][1] + bv1;
            float v2 = acc[mi][ni][2] + bv0;
            float v3 = acc[mi][ni][3] + bv1;
            if (act) {
                v0 = (v0 > 0.f) ? v0 : 0.01f * v0;
                v1 = (v1 > 0.f) ? v1 : 0.01f * v1;
                v2 = (v2 > 0.f) ? v2 : 0.01f * v2;
                v3 = (v3 > 0.f) ? v3 : 0.01f * v3;
            }
            if (hout) {
                __half* Ch = (__half*)Cv;
                *(__half2*)(Ch + (size_t)row * Nn + col) =
                    __halves2half2(__float2half_rn(v0), __float2half_rn(v1));
                *(__half2*)(Ch + (size_t)(row + 8) * Nn + col) =
                    __halves2half2(__float2half_rn(v2), __float2half_rn(v3));
            } else {
                float* Cf = (float*)Cv;
                Cf[(size_t)row * Nn + col]           = v0;
                Cf[(size_t)row * Nn + col + 1]       = v1;
                Cf[(size_t)(row + 8) * Nn + col]     = v2;
                Cf[(size_t)(row + 8) * Nn + col + 1] = v3;
            }
        }
    }
}

// ---------------- fp32/fp16-A SGEMM with z-pair fusion; fp32 or fp16 output ----------------
__global__ void sgemm_kernel(const void* __restrict__ Av,
                             const float* __restrict__ B0, const float* __restrict__ B1,
                             const float* __restrict__ bias0, const float* __restrict__ bias1,
                             void* __restrict__ C0v, void* __restrict__ C1v,
                             int M, int Nn, int K, int act, int hout, int ahalf) {
    __shared__ float As[8][128];
    __shared__ float Bs[8][128];
    const int bx = blockIdx.x * 128;
    const int by = blockIdx.y * 128;
    const int z  = blockIdx.z;
    const float* B = z ? B1 : B0;
    const float* bias = z ? bias1 : bias0;
    void* Cv = z ? C1v : C0v;
    const int tid = threadIdx.x;
    const int tr = tid / 16;
    const int tc = tid % 16;

    float acc[8][8];
#pragma unroll
    for (int i = 0; i < 8; i++)
#pragma unroll
        for (int j = 0; j < 8; j++) acc[i][j] = 0.f;

    const int row_a = tid / 2;
    const int cola0 = (tid % 2) * 4;
    const int row_b = tid / 32;
    const int colb0 = (tid % 32) * 4;

    for (int k0 = 0; k0 < K; k0 += 8) {
#pragma unroll
        for (int i = 0; i < 4; i++) {
            int r = by + row_a;
            int kk = k0 + cola0 + i;
            float av = 0.f;
            if (r < M && kk < K) {
                av = ahalf ? __half2float(((const __half*)Av)[(size_t)r * K + kk])
                           : ((const float*)Av)[(size_t)r * K + kk];
            }
            As[cola0 + i][row_a] = av;
        }
#pragma unroll
        for (int i = 0; i < 4; i++) {
            int kk = k0 + row_b;
            int c = bx + colb0 + i;
            Bs[row_b][colb0 + i] = (kk < K && c < Nn) ? B[(size_t)kk * Nn + c] : 0.f;
        }
        __syncthreads();
#pragma unroll
        for (int kk = 0; kk < 8; kk++) {
            float a[8], b[8];
#pragma unroll
            for (int i = 0; i < 8; i++) a[i] = As[kk][tr + 16 * i];
#pragma unroll
            for (int j = 0; j < 8; j++) b[j] = Bs[kk][tc + 16 * j];
#pragma unroll
            for (int i = 0; i < 8; i++)
#pragma unroll
                for (int j = 0; j < 8; j++) acc[i][j] += a[i] * b[j];
        }
        __syncthreads();
    }

#pragma unroll
    for (int i = 0; i < 8; i++) {
        int r = by + tr + 16 * i;
        if (r >= M) continue;
#pragma unroll
        for (int j = 0; j < 8; j++) {
            int c = bx + tc + 16 * j;
            if (c >= Nn) continue;
            float v = acc[i][j] + bias[c];
            if (act) v = (v > 0.f) ? v : 0.01f * v;
            if (hout) ((__half*)Cv)[(size_t)r * Nn + c] = __float2half_rn(v);
            else      ((float*)Cv)[(size_t)r * Nn + c] = v;
        }
    }
}

// ---------------- fused score + softmax: one warp per (dst, head), CSR order ----------------
// Writes g_alpha[e*HH+h] = exp(score - max) / (sum * HH)  (fully normalized).
__global__ __launch_bounds__(256) void score_softmax_kernel(
    const float* __restrict__ att, int C) {
    const int wid = threadIdx.x >> 5, lane = threadIdx.x & 31;
    const int gw = blockIdx.x * 8 + wid;
    if (gw >= NN * HH) return;
    const int d = gw >> 5;          // / HH (HH==32)
    const int h = gw & 31;
    const int r0 = g_rowptr[d], r1 = g_rowptr[d + 1];
    const int deg = r1 - r0;
    __shared__ float s_sc[8][64];

    const __half* xr = g_xr + ((size_t)d * HH + h) * C;
    const float*  at = att + h * C;

    for (int i0 = 0; i0 < deg; i0 += 4) {
        const int m = min(4, deg - i0);
        const __half* xp[4];
#pragma unroll
        for (int j = 0; j < 4; j++) {
            int e = g_eid[r0 + i0 + ((j < m) ? j : 0)];
            xp[j] = g_xl + ((size_t)g_src[e] * HH + h) * C;
        }
        float a0 = 0.f, a1 = 0.f, a2 = 0.f, a3 = 0.f;
        for (int c = lane; c < C; c += 32) {
            float xrv = __half2float(xr[c]);
            float wv  = at[c];
            float v;
            v = __half2float(xp[0][c]) + xrv; v = (v > 0.f) ? v : 0.2f * v; a0 += wv * v;
            if (m > 1) { v = __half2float(xp[1][c]) + xrv; v = (v > 0.f) ? v : 0.2f * v; a1 += wv * v; }
            if (m > 2) { v = __half2float(xp[2][c]) + xrv; v = (v > 0.f) ? v : 0.2f * v; a2 += wv * v; }
            if (m > 3) { v = __half2float(xp[3][c]) + xrv; v = (v > 0.f) ? v : 0.2f * v; a3 += wv * v; }
        }
#pragma unroll
        for (int o = 16; o; o >>= 1) {
            a0 += __shfl_xor_sync(0xffffffffu, a0, o);
            a1 += __shfl_xor_sync(0xffffffffu, a1, o);
            a2 += __shfl_xor_sync(0xffffffffu, a2, o);
            a3 += __shfl_xor_sync(0xffffffffu, a3, o);
        }
        if (lane == 0) {
            s_sc[wid][i0] = a0;
            if (m > 1) s_sc[wid][i0 + 1] = a1;
            if (m > 2) s_sc[wid][i0 + 2] = a2;
            if (m > 3) s_sc[wid][i0 + 3] = a3;
        }
    }
    __syncwarp();

    float mx = -1e30f;
    for (int i = lane; i < deg; i += 32) mx = fmaxf(mx, s_sc[wid][i]);
#pragma unroll
    for (int o = 16; o; o >>= 1) mx = fmaxf(mx, __shfl_xor_sync(0xffffffffu, mx, o));
    float sm = 0.f;
    for (int i = lane; i < deg; i += 32) sm += expf(s_sc[wid][i] - mx);
#pragma unroll
    for (int o = 16; o; o >>= 1) sm += __shfl_xor_sync(0xffffffffu, sm, o);
    const float inv = 1.0f / (sm * (float)HH);
    for (int i = lane; i < deg; i += 32) {
        int e = g_eid[r0 + i];
        g_alpha[e * HH + h] = expf(s_sc[wid][i] - mx) * inv;
    }
}

// ---------------- CSR aggregation (fp16 x, pre-normalized alpha) -> fp16 g_ah [NN,Kp] ----------------
__global__ void aggregate_kernel(const float* __restrict__ bias,
                                 __half* __restrict__ out, int C, int Kp, int act) {
    const int n = blockIdx.x;
    const int c = blockIdx.y * 128 + threadIdx.x;
    const int tid = threadIdx.x;
    __shared__ float sw[64 * HH];
    __shared__ int   sid[64];
    const int r0 = g_rowptr[n], r1 = g_rowptr[n + 1];
    float acc = 0.f;
    for (int r = r0; r < r1; r += 64) {
        int cd = min(64, r1 - r);
        __syncthreads();
        for (int i = tid; i < cd * HH; i += 128) {
            int le = i >> 5, h = i & 31;
            int e = g_eid[r + le];
            sw[i] = g_alpha[e * HH + h];
        }
        if (tid < cd) sid[tid] = g_src[g_eid[r + tid]];
        __syncthreads();
        if (c < C) {
            for (int le = 0; le < cd; le++) {
                const __half* xrow = g_xl + (size_t)sid[le] * HH * C + c;
                const float* wrow = sw + le * HH;
#pragma unroll 4
                for (int h = 0; h < HH; h++)
                    acc += wrow[h] * __half2float(xrow[(size_t)h * C]);
            }
        }
    }
    if (c < Kp) {
        float v = 0.f;
        if (c < C) {
            v = acc + bias[c];
            if (act) v = (v > 0.f) ? v : 0.01f * v;
        }
        out[(size_t)n * Kp + c] = __float2half_rn(v);
    }
}

// ---------------- host-side orchestration ----------------
static __half *h_ah, *h_b0, *h_b1;

static void run_tc_pair(const float* B0, const float* bias0, void* C0,
                        const float* B1, const float* bias1, void* C1,
                        int M, int Nn, int K, int Kp, int act, int nz, int hout) {
    int n4 = (Kp * Nn) >> 2;
    convertB_kernel<<<dim3((n4 + 255) / 256, nz), 256>>>(B0, B1 ? B1 : B0, K, Nn, Kp);
    cudaFuncSetAttribute(tc_gemm_kernel, cudaFuncAttributeMaxDynamicSharedMemorySize, DSMEM);
    dim3 grid(Nn / 128, M / 128, nz);
    tc_gemm_kernel<<<grid, 256, DSMEM>>>(h_ah, h_b0, h_b1,
                                         bias0, bias1 ? bias1 : bias0,
                                         C0, C1 ? C1 : C0, Nn, Kp, act, hout);
}

// attention: fused score+softmax, then aggregation -> fp16 g_ah [NN, Kp]
static void gat_attention(const float* att, const float* gb,
                          int Cout, int Kp, int act_after) {
    score_softmax_kernel<<<(NN * HH) / 8, 256>>>(att, Cout);
    aggregate_kernel<<<dim3(NN, (Kp + 127) / 128), 128>>>(gb, h_ah, Cout, Kp, act_after);
}

extern "C" void kernel_launch(void* const* d_in, const int* in_sizes, int n_in,
                              void* d_out, int out_size) {
    const float* x  = (const float*)d_in[0];
    const void*  ei = d_in[1];
    const float* w1l = (const float*)d_in[2];
    const float* b1l = (const float*)d_in[3];
    const float* w1r = (const float*)d_in[4];
    const float* b1r = (const float*)d_in[5];
    const float* att1 = (const float*)d_in[6];
    const float* gb1  = (const float*)d_in[7];
    const float* w2l = (const float*)d_in[8];
    const float* b2l = (const float*)d_in[9];
    const float* w2r = (const float*)d_in[10];
    const float* b2r = (const float*)d_in[11];
    const float* att2 = (const float*)d_in[12];
    const float* gb2  = (const float*)d_in[13];
    const float* w3l = (const float*)d_in[14];
    const float* b3l = (const float*)d_in[15];
    const float* w3r = (const float*)d_in[16];
    const float* b3r = (const float*)d_in[17];
    const float* att3 = (const float*)d_in[18];
    const float* gb3  = (const float*)d_in[19];
    const float* dw1 = (const float*)d_in[20];
    const float* db1 = (const float*)d_in[21];
    const float* dw2 = (const float*)d_in[22];
    const float* db2 = (const float*)d_in[23];
    const float* dw3 = (const float*)d_in[24];
    const float* db3 = (const float*)d_in[25];

    void* p;
    cudaGetSymbolAddress(&p, g_xl);   __half* xl = (__half*)p;
    cudaGetSymbolAddress(&p, g_xr);   __half* xr = (__half*)p;
    cudaGetSymbolAddress(&p, g_ah);   h_ah = (__half*)p;
    cudaGetSymbolAddress(&p, g_b0);   h_b0 = (__half*)p;
    cudaGetSymbolAddress(&p, g_b1);   h_b1 = (__half*)p;

    // edges (dtype-robust) + CSR
    detect_dtype_kernel<<<1, 256>>>(ei);
    build_edges_kernel<<<(ET + 255) / 256, 256>>>(ei);
    csr_rank_kernel<<<(ET + 255) / 256, 256>>>();
    csr_scan_place_kernel<<<1, NN>>>();

    // ---- GAT layer 1 (Cin=4, fp32 pair GEMM, fp16 out), Cout=128
    sgemm_kernel<<<dim3(32, 8, 2), 256>>>(x, w1l, w1r, b1l, b1r, xl, xr,
                                          NN, HH * 128, 4, 0, 1, 0);
    gat_attention(att1, gb1, 128, 128, 1);          // -> g_ah [1024,128] fp16

    // ---- GAT layer 2: Cin=128 (Kp=128), Cout=512
    run_tc_pair(w2l, b2l, xl, w2r, b2r, xr, NN, HH * 512, 128, 128, 0, 2, 1);
    gat_attention(att2, gb2, 512, 512, 1);          // -> g_ah [1024,512] fp16

    // ---- GAT layer 3: Cin=512 (Kp=512), Cout=1028
    run_tc_pair(w3l, b3l, xl, w3r, b3r, xr, NN, HH * 1028, 512, 512, 0, 2, 1);
    gat_attention(att3, gb3, 1028, 1088, 0);        // -> g_ah [1024,1088] fp16 (padded)

    // ---- decoder MLP: GEMMs write fp16 A for the next stage directly
    run_tc_pair(dw1, db1, h_ah, 0, 0, 0, NN, 512, 1028, 1088, 1, 1, 1);  // -> g_ah [1024,512]
    run_tc_pair(dw2, db2, h_ah, 0, 0, 0, NN, 128, 512, 512, 1, 1, 1);    // -> g_ah [1024,128]
    sgemm_kernel<<<dim3(1, 8, 1), 256>>>(h_ah, dw3, dw3, db3, db3,
                                         d_out, d_out, NN, 2, 128, 0, 0, 1);

    (void)in_sizes; (void)n_in; (void)out_size;
}

// round 14
// speedup vs baseline: 1.2339x; 1.2339x over previous
#include <cuda_runtime.h>
#include <cuda_fp16.h>
#include <cstdint>

#define NN   1024      // nodes
#define EE   2048      // raw edges
#define ET   3072      // edges + self loops
#define HH   32        // heads
#define CMX  1028      // max per-head channel dim
#define KPMX 1088      // max padded K
#define BMAX 16842752  // 32896*512 max weight elements

// ---------------- scratch (device globals; no allocation allowed) ----------------
__device__ __half   g_xl[(size_t)NN * HH * CMX];
__device__ __half   g_xr[(size_t)NN * HH * CMX];
__device__ float    g_score[ET * HH];
__device__ float    g_alpha[ET * HH];
__device__ int      g_src[ET];
__device__ int      g_dst[ET];
__device__ int      g_rank[ET];
__device__ int      g_deg[NN];
__device__ int      g_rowptr[NN + 1];
__device__ int      g_eid[ET];
__device__ int      g_is64;
__device__ __half   g_ah[NN * KPMX];
__device__ __half   g_b0[BMAX];
__device__ __half   g_b1[BMAX];

// ---------------- edge dtype detection ----------------
__global__ void detect_dtype_kernel(const void* ei) {
    __shared__ int bad;
    if (threadIdx.x == 0) bad = 0;
    __syncthreads();
    const long long* p = (const long long*)ei;
    for (int i = threadIdx.x; i < EE; i += blockDim.x) {
        long long v = p[i];
        if (v < 0 || v >= NN) bad = 1;
    }
    __syncthreads();
    if (threadIdx.x == 0) g_is64 = !bad;
}

// ---------------- edge build + deg zero ----------------
__global__ void build_edges_kernel(const void* ei) {
    int i = blockIdx.x * blockDim.x + threadIdx.x;
    if (i < ET) {
        if (i < EE) {
            if (g_is64) {
                const long long* p = (const long long*)ei;
                g_src[i] = (int)p[i];
                g_dst[i] = (int)p[EE + i];
            } else {
                const int* p = (const int*)ei;
                g_src[i] = p[i];
                g_dst[i] = p[EE + i];
            }
        } else {
            g_src[i] = i - EE;
            g_dst[i] = i - EE;
        }
    }
    if (i < NN) g_deg[i] = 0;
}

// ---------------- CSR build (deterministic) ----------------
__global__ void csr_rank_kernel() {
    __shared__ int sd[ET];
    int tid = threadIdx.x;
    for (int i = tid; i < ET; i += blockDim.x) sd[i] = g_dst[i];
    __syncthreads();
    int e = blockIdx.x * blockDim.x + tid;
    if (e < ET) {
        int d = sd[e], r = 0;
        for (int e2 = 0; e2 < e; e2++) r += (sd[e2] == d);
        g_rank[e] = r;
        atomicAdd(&g_deg[d], 1);
    }
}

// scan + place fused: single block of NN threads
__global__ void csr_scan_place_kernel() {
    __shared__ int s[NN];
    __shared__ int start[NN];
    int t = threadIdx.x;
    s[t] = g_deg[t];
    __syncthreads();
    for (int o = 1; o < NN; o <<= 1) {
        int v = (t >= o) ? s[t - o] : 0;
        __syncthreads();
        s[t] += v;
        __syncthreads();
    }
    g_rowptr[t + 1] = s[t];
    start[t] = s[t] - g_deg[t];
    if (t == 0) g_rowptr[0] = 0;
    __syncthreads();
    for (int e = t; e < ET; e += NN)
        g_eid[start[g_dst[e]] + g_rank[e]] = e;
}

// ---------------- fp32 [K,Nn] -> fp16, row pad to Kp; pair fused via blockIdx.y ----------------
__global__ void convertB_kernel(const float* __restrict__ B0,
                                const float* __restrict__ B1,
                                int K, int Nn, int Kp) {
    int i4 = blockIdx.x * blockDim.x + threadIdx.x;
    int tot = (Kp * Nn) >> 2;
    if (i4 >= tot) return;
    const float* src = blockIdx.y ? B1 : B0;
    __half* dst = blockIdx.y ? g_b1 : g_b0;
    int n4 = Nn >> 2;
    int r = i4 / n4, c4 = (i4 - r * n4) << 2;
    float v[4];
    if (r < K) {
        float4 f = *(const float4*)(src + (size_t)r * Nn + c4);
        v[0] = f.x; v[1] = f.y; v[2] = f.z; v[3] = f.w;
    } else {
        v[0] = v[1] = v[2] = v[3] = 0.f;
    }
    size_t o = (size_t)r * Nn + c4;
    *(__half2*)(dst + o)     = __halves2half2(__float2half_rn(v[0]), __float2half_rn(v[1]));
    *(__half2*)(dst + o + 2) = __halves2half2(__float2half_rn(v[2]), __float2half_rn(v[3]));
}

// ---------------- tensor-core GEMM (plain fp16, fp32 accum, cp.async pipeline) ----------------
#define ASTR 40
#define BSTR 136
#define AOFF 0
#define BOFF 10240
#define BUFSZ 18944
#define DSMEM (2 * BUFSZ)

#define LDMX4(R0,R1,R2,R3,ADDR) \
    asm volatile("ldmatrix.sync.aligned.m8n8.x4.shared.b16 {%0,%1,%2,%3}, [%4];" \
        : "=r"(R0), "=r"(R1), "=r"(R2), "=r"(R3) : "r"(ADDR))
#define LDMX2T(R0,R1,ADDR) \
    asm volatile("ldmatrix.sync.aligned.m8n8.x2.trans.shared.b16 {%0,%1}, [%2];" \
        : "=r"(R0), "=r"(R1) : "r"(ADDR))
#define MMA16816(C0,C1,C2,C3,A0,A1,A2,A3,B0,B1) \
    asm volatile("mma.sync.aligned.m16n8k16.row.col.f32.f16.f16.f32 " \
        "{%0,%1,%2,%3}, {%4,%5,%6,%7}, {%8,%9}, {%0,%1,%2,%3};" \
        : "+f"(C0), "+f"(C1), "+f"(C2), "+f"(C3) \
        : "r"(A0), "r"(A1), "r"(A2), "r"(A3), "r"(B0), "r"(B1))
#define CP16(SADDR, GPTR) \
    asm volatile("cp.async.ca.shared.global [%0], [%1], 16;" :: "r"(SADDR), "l"(GPTR))

__global__ __launch_bounds__(256) void tc_gemm_kernel(
    const __half* __restrict__ Ah,
    const __half* __restrict__ B0, const __half* __restrict__ B1,
    const float* __restrict__ bias0, const float* __restrict__ bias1,
    void* __restrict__ C0v, void* __restrict__ C1v,
    int Nn, int Kp, int act, int hout)
{
    extern __shared__ char smem[];
    const uint32_t sbase = (uint32_t)__cvta_generic_to_shared(smem);

    const int tid  = threadIdx.x;
    const int warp = tid >> 5;
    const int lane = tid & 31;
    const int wm = (warp >> 2) * 64;
    const int wn = (warp & 3) * 32;
    const int bx = blockIdx.x * 128;
    const int by = blockIdx.y * 128;
    const int z  = blockIdx.z;

    const __half* B = z ? B1 : B0;
    const float* bias = z ? bias1 : bias0;
    void* Cv = z ? C1v : C0v;

    float acc[4][4][4];
#pragma unroll
    for (int mi = 0; mi < 4; mi++)
#pragma unroll
        for (int ni = 0; ni < 4; ni++)
#pragma unroll
            for (int k = 0; k < 4; k++) acc[mi][ni][k] = 0.f;

    const int nc = Kp >> 5;

    auto load_tile = [&](int c, int b) {
        const int k0 = c << 5;
        const uint32_t base = sbase + b * BUFSZ;
#pragma unroll
        for (int j = 0; j < 2; j++) {
            int idx = tid + j * 256;
            int row = idx >> 2, seg = idx & 3;
            size_t go = (size_t)(by + row) * Kp + k0 + seg * 8;
            uint32_t so = base + (uint32_t)(row * ASTR + seg * 8) * 2;
            CP16(so + AOFF, Ah + go);
        }
#pragma unroll
        for (int j = 0; j < 2; j++) {
            int idx = tid + j * 256;
            int row = idx >> 4, seg = idx & 15;
            size_t go = (size_t)(k0 + row) * Nn + bx + seg * 8;
            uint32_t so = base + (uint32_t)(row * BSTR + seg * 8) * 2;
            CP16(so + BOFF, B + go);
        }
        asm volatile("cp.async.commit_group;" ::: "memory");
    };

    const int r8 = lane & 7;
    const int gA = lane >> 3;
    const int gB = (lane >> 3) & 1;

    load_tile(0, 0);

    for (int c = 0; c < nc; c++) {
        const int b = c & 1;
        if (c + 1 < nc) {
            load_tile(c + 1, (c + 1) & 1);
            asm volatile("cp.async.wait_group 1;" ::: "memory");
        } else {
            asm volatile("cp.async.wait_group 0;" ::: "memory");
        }
        __syncthreads();

        const uint32_t base = sbase + b * BUFSZ;
#pragma unroll
        for (int ks = 0; ks < 2; ks++) {
            const int ko = ks * 16;
            uint32_t ah[4][4], bb[4][2];
#pragma unroll
            for (int mi = 0; mi < 4; mi++) {
                int row = wm + mi * 16 + r8 + (gA & 1) * 8;
                int col = ko + (gA >> 1) * 8;
                uint32_t off = (uint32_t)(row * ASTR + col) * 2;
                LDMX4(ah[mi][0], ah[mi][1], ah[mi][2], ah[mi][3], base + AOFF + off);
            }
#pragma unroll
            for (int ni = 0; ni < 4; ni++) {
                int row = ko + gB * 8 + r8;
                int col = wn + ni * 8;
                uint32_t off = (uint32_t)(row * BSTR + col) * 2;
                LDMX2T(bb[ni][0], bb[ni][1], base + BOFF + off);
            }
#pragma unroll
            for (int mi = 0; mi < 4; mi++) {
#pragma unroll
                for (int ni = 0; ni < 4; ni++) {
                    float* cc = acc[mi][ni];
                    MMA16816(cc[0], cc[1], cc[2], cc[3],
                             ah[mi][0], ah[mi][1], ah[mi][2], ah[mi][3],
                             bb[ni][0], bb[ni][1]);
                }
            }
        }
        __syncthreads();
    }

    const int g = lane >> 2, tig = lane & 3;
#pragma unroll
    for (int mi = 0; mi < 4; mi++) {
#pragma unroll
        for (int ni = 0; ni < 4; ni++) {
            int row = by + wm + mi * 16 + g;
            int col = bx + wn + ni * 8 + tig * 2;
            float bv0 = bias[col], bv1 = bias[col + 1];
            float v0 = acc[mi][ni][0] + bv0;
            float v1 = acc[mi][ni][1] + bv1;
            float v2 = acc[mi][ni][2] + bv0;
            float v3 = acc[mi][ni][3] + bv1;
            if (act) {
                v0 = (v0 > 0.f) ? v0 : 0.01f * v0;
                v1 = (v1 > 0.f) ? v1 : 0.01f * v1;
                v2 = (v2 > 0.f) ? v2 : 0.01f * v2;
                v3 = (v3 > 0.f) ? v3 : 0.01f * v3;
            }
            if (hout) {
                __half* Ch = (__half*)Cv;
                *(__half2*)(Ch + (size_t)row * Nn + col) =
                    __halves2half2(__float2half_rn(v0), __float2half_rn(v1));
                *(__half2*)(Ch + (size_t)(row + 8) * Nn + col) =
                    __halves2half2(__float2half_rn(v2), __float2half_rn(v3));
            } else {
                float* Cf = (float*)Cv;
                Cf[(size_t)row * Nn + col]           = v0;
                Cf[(size_t)row * Nn + col + 1]       = v1;
                Cf[(size_t)(row + 8) * Nn + col]     = v2;
                Cf[(size_t)(row + 8) * Nn + col + 1] = v3;
            }
        }
    }
}

// ---------------- fp32/fp16-A SGEMM with z-pair fusion; fp32 or fp16 output ----------------
__global__ void sgemm_kernel(const void* __restrict__ Av,
                             const float* __restrict__ B0, const float* __restrict__ B1,
                             const float* __restrict__ bias0, const float* __restrict__ bias1,
                             void* __restrict__ C0v, void* __restrict__ C1v,
                             int M, int Nn, int K, int act, int hout, int ahalf) {
    __shared__ float As[8][128];
    __shared__ float Bs[8][128];
    const int bx = blockIdx.x * 128;
    const int by = blockIdx.y * 128;
    const int z  = blockIdx.z;
    const float* B = z ? B1 : B0;
    const float* bias = z ? bias1 : bias0;
    void* Cv = z ? C1v : C0v;
    const int tid = threadIdx.x;
    const int tr = tid / 16;
    const int tc = tid % 16;

    float acc[8][8];
#pragma unroll
    for (int i = 0; i < 8; i++)
#pragma unroll
        for (int j = 0; j < 8; j++) acc[i][j] = 0.f;

    const int row_a = tid / 2;
    const int cola0 = (tid % 2) * 4;
    const int row_b = tid / 32;
    const int colb0 = (tid % 32) * 4;

    for (int k0 = 0; k0 < K; k0 += 8) {
#pragma unroll
        for (int i = 0; i < 4; i++) {
            int r = by + row_a;
            int kk = k0 + cola0 + i;
            float av = 0.f;
            if (r < M && kk < K) {
                av = ahalf ? __half2float(((const __half*)Av)[(size_t)r * K + kk])
                           : ((const float*)Av)[(size_t)r * K + kk];
            }
            As[cola0 + i][row_a] = av;
        }
#pragma unroll
        for (int i = 0; i < 4; i++) {
            int kk = k0 + row_b;
            int c = bx + colb0 + i;
            Bs[row_b][colb0 + i] = (kk < K && c < Nn) ? B[(size_t)kk * Nn + c] : 0.f;
        }
        __syncthreads();
#pragma unroll
        for (int kk = 0; kk < 8; kk++) {
            float a[8], b[8];
#pragma unroll
            for (int i = 0; i < 8; i++) a[i] = As[kk][tr + 16 * i];
#pragma unroll
            for (int j = 0; j < 8; j++) b[j] = Bs[kk][tc + 16 * j];
#pragma unroll
            for (int i = 0; i < 8; i++)
#pragma unroll
                for (int j = 0; j < 8; j++) acc[i][j] += a[i] * b[j];
        }
        __syncthreads();
    }

#pragma unroll
    for (int i = 0; i < 8; i++) {
        int r = by + tr + 16 * i;
        if (r >= M) continue;
#pragma unroll
        for (int j = 0; j < 8; j++) {
            int c = bx + tc + 16 * j;
            if (c >= Nn) continue;
            float v = acc[i][j] + bias[c];
            if (act) v = (v > 0.f) ? v : 0.01f * v;
            if (hout) ((__half*)Cv)[(size_t)r * Nn + c] = __float2half_rn(v);
            else      ((float*)Cv)[(size_t)r * Nn + c] = v;
        }
    }
}

// ---------------- per-(edge,head) attention score (fp16 inputs, uint2 loads) ----------------
__global__ void score_kernel(const float* __restrict__ att, int C) {
    int gw = (blockIdx.x * blockDim.x + threadIdx.x) >> 5;
    int lane = threadIdx.x & 31;
    if (gw >= ET * HH) return;
    int e = gw / HH, h = gw % HH;
    int s = g_src[e], d = g_dst[e];
    const int n4 = C >> 2;
    const uint2* xl = (const uint2*)(g_xl + ((size_t)s * HH + h) * C);
    const uint2* xr = (const uint2*)(g_xr + ((size_t)d * HH + h) * C);
    const float4* at = (const float4*)(att + h * C);
    float acc = 0.f;
    for (int c = lane; c < n4; c += 32) {
        uint2 ua = xl[c], ub = xr[c];
        float2 a0 = __half22float2(*(__half2*)&ua.x);
        float2 a1 = __half22float2(*(__half2*)&ua.y);
        float2 b0 = __half22float2(*(__half2*)&ub.x);
        float2 b1 = __half22float2(*(__half2*)&ub.y);
        float4 w = at[c];
        float v0 = a0.x + b0.x, v1 = a0.y + b0.y;
        float v2 = a1.x + b1.x, v3 = a1.y + b1.y;
        v0 = (v0 > 0.f) ? v0 : 0.2f * v0;
        v1 = (v1 > 0.f) ? v1 : 0.2f * v1;
        v2 = (v2 > 0.f) ? v2 : 0.2f * v2;
        v3 = (v3 > 0.f) ? v3 : 0.2f * v3;
        acc += w.x * v0 + w.y * v1 + w.z * v2 + w.w * v3;
    }
#pragma unroll
    for (int o = 16; o; o >>= 1) acc += __shfl_xor_sync(0xffffffffu, acc, o);
    if (lane == 0) g_score[e * HH + h] = acc;
}

// ---------------- CSR softmax: one thread per (dst, head); writes normalized alpha ----------------
__global__ void softmax_kernel() {
    int i = blockIdx.x * blockDim.x + threadIdx.x;
    if (i >= NN * HH) return;
    int d = i >> 5, h = i & 31;       // HH == 32
    int r0 = g_rowptr[d], r1 = g_rowptr[d + 1];
    float mx = -1e30f;
    for (int r = r0; r < r1; r++)
        mx = fmaxf(mx, g_score[g_eid[r] * HH + h]);
    float sm = 0.f;
    for (int r = r0; r < r1; r++)
        sm += expf(g_score[g_eid[r] * HH + h] - mx);
    float inv = 1.0f / (sm * (float)HH);
    for (int r = r0; r < r1; r++) {
        int e = g_eid[r];
        g_alpha[e * HH + h] = expf(g_score[e * HH + h] - mx) * inv;
    }
}

// ---------------- CSR aggregation (fp16 x, pre-normalized alpha) -> fp16 g_ah [NN,Kp] ----------------
__global__ void aggregate_kernel(const float* __restrict__ bias,
                                 __half* __restrict__ out, int C, int Kp, int act) {
    const int n = blockIdx.x;
    const int c = blockIdx.y * 128 + threadIdx.x;
    const int tid = threadIdx.x;
    __shared__ float sw[64 * HH];
    __shared__ int   sid[64];
    const int r0 = g_rowptr[n], r1 = g_rowptr[n + 1];
    float acc = 0.f;
    for (int r = r0; r < r1; r += 64) {
        int cd = min(64, r1 - r);
        __syncthreads();
        for (int i = tid; i < cd * HH; i += 128) {
            int le = i >> 5, h = i & 31;
            int e = g_eid[r + le];
            sw[i] = g_alpha[e * HH + h];
        }
        if (tid < cd) sid[tid] = g_src[g_eid[r + tid]];
        __syncthreads();
        if (c < C) {
            for (int le = 0; le < cd; le++) {
                const __half* xrow = g_xl + (size_t)sid[le] * HH * C + c;
                const float* wrow = sw + le * HH;
#pragma unroll 4
                for (int h = 0; h < HH; h++)
                    acc += wrow[h] * __half2float(xrow[(size_t)h * C]);
            }
        }
    }
    if (c < Kp) {
        float v = 0.f;
        if (c < C) {
            v = acc + bias[c];
            if (act) v = (v > 0.f) ? v : 0.01f * v;
        }
        out[(size_t)n * Kp + c] = __float2half_rn(v);
    }
}

// ---------------- host-side orchestration ----------------
static __half *h_ah, *h_b0, *h_b1;

static void run_tc_pair(const float* B0, const float* bias0, void* C0,
                        const float* B1, const float* bias1, void* C1,
                        int M, int Nn, int K, int Kp, int act, int nz, int hout) {
    int n4 = (Kp * Nn) >> 2;
    convertB_kernel<<<dim3((n4 + 255) / 256, nz), 256>>>(B0, B1 ? B1 : B0, K, Nn, Kp);
    cudaFuncSetAttribute(tc_gemm_kernel, cudaFuncAttributeMaxDynamicSharedMemorySize, DSMEM);
    dim3 grid(Nn / 128, M / 128, nz);
    tc_gemm_kernel<<<grid, 256, DSMEM>>>(h_ah, h_b0, h_b1,
                                         bias0, bias1 ? bias1 : bias0,
                                         C0, C1 ? C1 : C0, Nn, Kp, act, hout);
}

// attention: edge-parallel score, CSR softmax, aggregation -> fp16 g_ah [NN, Kp]
static void gat_attention(const float* att, const float* gb,
                          int Cout, int Kp, int act_after) {
    score_kernel<<<(ET * HH) / 8, 256>>>(att, Cout);
    softmax_kernel<<<(NN * HH) / 256, 256>>>();
    aggregate_kernel<<<dim3(NN, (Kp + 127) / 128), 128>>>(gb, h_ah, Cout, Kp, act_after);
}

extern "C" void kernel_launch(void* const* d_in, const int* in_sizes, int n_in,
                              void* d_out, int out_size) {
    const float* x  = (const float*)d_in[0];
    const void*  ei = d_in[1];
    const float* w1l = (const float*)d_in[2];
    const float* b1l = (const float*)d_in[3];
    const float* w1r = (const float*)d_in[4];
    const float* b1r = (const float*)d_in[5];
    const float* att1 = (const float*)d_in[6];
    const float* gb1  = (const float*)d_in[7];
    const float* w2l = (const float*)d_in[8];
    const float* b2l = (const float*)d_in[9];
    const float* w2r = (const float*)d_in[10];
    const float* b2r = (const float*)d_in[11];
    const float* att2 = (const float*)d_in[12];
    const float* gb2  = (const float*)d_in[13];
    const float* w3l = (const float*)d_in[14];
    const float* b3l = (const float*)d_in[15];
    const float* w3r = (const float*)d_in[16];
    const float* b3r = (const float*)d_in[17];
    const float* att3 = (const float*)d_in[18];
    const float* gb3  = (const float*)d_in[19];
    const float* dw1 = (const float*)d_in[20];
    const float* db1 = (const float*)d_in[21];
    const float* dw2 = (const float*)d_in[22];
    const float* db2 = (const float*)d_in[23];
    const float* dw3 = (const float*)d_in[24];
    const float* db3 = (const float*)d_in[25];

    void* p;
    cudaGetSymbolAddress(&p, g_xl);   __half* xl = (__half*)p;
    cudaGetSymbolAddress(&p, g_xr);   __half* xr = (__half*)p;
    cudaGetSymbolAddress(&p, g_ah);   h_ah = (__half*)p;
    cudaGetSymbolAddress(&p, g_b0);   h_b0 = (__half*)p;
    cudaGetSymbolAddress(&p, g_b1);   h_b1 = (__half*)p;

    // edges (dtype-robust) + CSR
    detect_dtype_kernel<<<1, 256>>>(ei);
    build_edges_kernel<<<(ET + 255) / 256, 256>>>(ei);
    csr_rank_kernel<<<(ET + 255) / 256, 256>>>();
    csr_scan_place_kernel<<<1, NN>>>();

    // ---- GAT layer 1 (Cin=4, fp32 pair GEMM, fp16 out), Cout=128
    sgemm_kernel<<<dim3(32, 8, 2), 256>>>(x, w1l, w1r, b1l, b1r, xl, xr,
                                          NN, HH * 128, 4, 0, 1, 0);
    gat_attention(att1, gb1, 128, 128, 1);          // -> g_ah [1024,128] fp16

    // ---- GAT layer 2: Cin=128 (Kp=128), Cout=512
    run_tc_pair(w2l, b2l, xl, w2r, b2r, xr, NN, HH * 512, 128, 128, 0, 2, 1);
    gat_attention(att2, gb2, 512, 512, 1);          // -> g_ah [1024,512] fp16

    // ---- GAT layer 3: Cin=512 (Kp=512), Cout=1028
    run_tc_pair(w3l, b3l, xl, w3r, b3r, xr, NN, HH * 1028, 512, 512, 0, 2, 1);
    gat_attention(att3, gb3, 1028, 1088, 0);        // -> g_ah [1024,1088] fp16 (padded)

    // ---- decoder MLP: GEMMs write fp16 A for the next stage directly
    run_tc_pair(dw1, db1, h_ah, 0, 0, 0, NN, 512, 1028, 1088, 1, 1, 1);  // -> g_ah [1024,512]
    run_tc_pair(dw2, db2, h_ah, 0, 0, 0, NN, 128, 512, 512, 1, 1, 1);    // -> g_ah [1024,128]
    sgemm_kernel<<<dim3(1, 8, 1), 256>>>(h_ah, dw3, dw3, db3, db3,
                                         d_out, d_out, NN, 2, 128, 0, 0, 1);

    (void)in_sizes; (void)n_in; (void)out_size;
}